// round 6
// baseline (speedup 1.0000x reference)
#include <cuda_runtime.h>
#include <math.h>

#define Bsz   2048
#define Fdim  128
#define Hdim  512
#define Tlen  96
#define G3H   1536
#define Mtile 16
#define KB    16
#define NTHREADS 256

typedef unsigned long long ull;

// Transposed weights (k-major) in device scratch, ~4MB, L2-resident.
__device__ __align__(16) float d_WhhT[Hdim * G3H];  // [k][n] k<512, n<1536
__device__ __align__(16) float d_WihT[Fdim * G3H];  // [k][n] k<128, n<1536
__device__ __align__(16) float d_FcwT[Hdim * Fdim]; // [k][f] k<512, f<128

// ---- packed f32x2 helpers ----
__device__ __forceinline__ ull bcast2(float a) {
    ull r; unsigned int u = __float_as_uint(a);
    asm("mov.b64 %0, {%1, %1};" : "=l"(r) : "r"(u));
    return r;
}
__device__ __forceinline__ void fma2(ull& d, ull a, ull b) {
    asm("fma.rn.f32x2 %0, %1, %2, %0;" : "+l"(d) : "l"(a), "l"(b));
}
__device__ __forceinline__ float2 unpack2(ull v) {
    unsigned int lo, hi;
    asm("mov.b64 {%0, %1}, %2;" : "=r"(lo), "=r"(hi) : "l"(v));
    return make_float2(__uint_as_float(lo), __uint_as_float(hi));
}

// ---- cp.async helpers ----
__device__ __forceinline__ void cp16(unsigned int s, const float* g) {
    asm volatile("cp.async.cg.shared.global [%0], [%1], 16;" :: "r"(s), "l"(g));
}
__device__ __forceinline__ void cp_commit() { asm volatile("cp.async.commit_group;" ::: "memory"); }
__device__ __forceinline__ void cp_wait1()  { asm volatile("cp.async.wait_group 1;" ::: "memory"); }

// One-time weight transpose
__global__ void gru_setup_kernel(const float* __restrict__ w_ih,
                                 const float* __restrict__ w_hh,
                                 const float* __restrict__ fc_w) {
    int idx = blockIdx.x * blockDim.x + threadIdx.x;
    if (idx < Hdim * G3H) {
        int k = idx / G3H, n = idx - k * G3H;
        d_WhhT[idx] = w_hh[n * Hdim + k];
    }
    int i2 = idx - Hdim * G3H;
    if (i2 >= 0 && i2 < Fdim * G3H) {
        int k = i2 / G3H, n = i2 - k * G3H;
        d_WihT[i2] = w_ih[n * Fdim + k];
    }
    int i3 = idx - Hdim * G3H - Fdim * G3H;
    if (i3 >= 0 && i3 < Hdim * Fdim) {
        int k = i3 / Fdim, f = i3 - k * Fdim;
        d_FcwT[i3] = fc_w[f * Hdim + k];
    }
}

// Stage KB k-rows x 768 cols (3 gate segments of 256) of gate weights into SMEM.
// Block b<8 -> WihT (k0=b*KB), else WhhT (k0=(b-8)*KB). 3072 16B units, 12/thread.
__device__ __forceinline__ void stage_gate(unsigned int wst_s, int bufi, int b, int nc, int tid) {
    const float* Wt; int k0;
    if (b < 8) { Wt = d_WihT; k0 = b * KB; }
    else       { Wt = d_WhhT; k0 = (b - 8) * KB; }
    unsigned int sb = wst_s + (unsigned int)bufi * (KB * 768 * 4);
    #pragma unroll
    for (int r = 0; r < 12; ++r) {
        int u = tid + r * NTHREADS;      // 0..3071
        int k = u / 192;                 // 192 16B-units per k-row
        int j = u - k * 192;
        int seg = j >> 6;                // gate segment 0..2
        int off = j & 63;                // 16B unit within 256-float segment
        const float* g = Wt + (size_t)(k0 + k) * G3H + seg * 512 + nc * 256 + off * 4;
        cp16(sb + (unsigned int)u * 16, g);
    }
}

// Stage KB k-rows x 128 cols of fc weights. 512 16B units, 2/thread.
__device__ __forceinline__ void stage_fc(unsigned int wst_s, int bufi, int b, int tid) {
    unsigned int sb = wst_s + (unsigned int)bufi * (KB * 768 * 4);
    int k0 = b * KB;
    #pragma unroll
    for (int r = 0; r < 2; ++r) {
        int u = tid + r * NTHREADS;      // 0..511
        int k = u >> 5;                  // 32 units per k-row
        int off = u & 31;
        const float* g = d_FcwT + (size_t)(k0 + k) * Fdim + off * 4;
        cp16(sb + (unsigned int)u * 16, g);
    }
}

// Compute one staged KB-block of the gate GEMMs. Per-thread tile: 8m x 2n (packed).
__device__ __forceinline__ void gate_block(
    const float* wb, const float* in, int ld, int bk, int mg, int ng2,
    ull (&aR)[8], ull (&aZ)[8], ull (&aX)[8])
{
    #pragma unroll
    for (int k4 = 0; k4 < 4; ++k4) {
        float4 av[8];
        #pragma unroll
        for (int i = 0; i < 8; ++i)
            av[i] = *reinterpret_cast<const float4*>(&in[(mg * 8 + i) * ld + bk + k4 * 4]);
        #pragma unroll
        for (int kk = 0; kk < 4; ++kk) {
            const float* w = wb + (k4 * 4 + kk) * 768 + ng2;
            ull wr = *reinterpret_cast<const ull*>(w);
            ull wz = *reinterpret_cast<const ull*>(w + 256);
            ull wn = *reinterpret_cast<const ull*>(w + 512);
            #pragma unroll
            for (int i = 0; i < 8; ++i) {
                const float* ap = reinterpret_cast<const float*>(&av[i]);
                ull a2 = bcast2(ap[kk]);
                fma2(aR[i], a2, wr);
                fma2(aZ[i], a2, wz);
                fma2(aX[i], a2, wn);
            }
        }
    }
}

// One staged KB-block of the fc GEMM. Per-thread tile: 2m x 4f.
__device__ __forceinline__ void fc_block(const float* wb, const float* hsrc,
                                         int bk, int mh, int f0, ull (&acc)[2][2]) {
    #pragma unroll
    for (int k4 = 0; k4 < 4; ++k4) {
        float4 av[2];
        #pragma unroll
        for (int i = 0; i < 2; ++i)
            av[i] = *reinterpret_cast<const float4*>(&hsrc[(mh * 2 + i) * Hdim + bk + k4 * 4]);
        #pragma unroll
        for (int kk = 0; kk < 4; ++kk) {
            const float* w = wb + (k4 * 4 + kk) * Fdim + f0;
            ulonglong2 wv = *reinterpret_cast<const ulonglong2*>(w);
            #pragma unroll
            for (int i = 0; i < 2; ++i) {
                const float* ap = reinterpret_cast<const float*>(&av[i]);
                ull a2 = bcast2(ap[kk]);
                fma2(acc[i][0], a2, wv.x);
                fma2(acc[i][1], a2, wv.y);
            }
        }
    }
}

__global__ __launch_bounds__(NTHREADS, 1)
void gru_kernel(const float* __restrict__ hidden,
                const float* __restrict__ b_ih,
                const float* __restrict__ b_hh,
                const float* __restrict__ fc_b,
                float* __restrict__ out) {
    extern __shared__ float smem[];
    float* hbufA = smem;                          // Mtile*Hdim
    float* hbufB = hbufA + Mtile * Hdim;          // Mtile*Hdim
    float* xbuf  = hbufB + Mtile * Hdim;          // Mtile*Fdim
    float* brz   = xbuf + Mtile * Fdim;           // 2*Hdim
    float* bin   = brz + 2 * Hdim;                // Hdim
    float* bhn   = bin + Hdim;                    // Hdim
    float* fcb   = bhn + Hdim;                    // Fdim
    float* wst   = fcb + Fdim;                    // 2 * KB*768 floats staging

    const int tid = threadIdx.x;
    const int m0  = blockIdx.x * Mtile;

    // ---- init shared state ----
    for (int i = tid; i < Mtile * Hdim; i += NTHREADS) hbufA[i] = hidden[m0 * Hdim + i];
    for (int i = tid; i < Mtile * Fdim; i += NTHREADS) xbuf[i] = 0.f;
    for (int i = tid; i < 2 * Hdim; i += NTHREADS)     brz[i] = b_ih[i] + b_hh[i];
    for (int i = tid; i < Hdim; i += NTHREADS) {
        bin[i] = b_ih[2 * Hdim + i];
        bhn[i] = b_hh[2 * Hdim + i];
    }
    for (int i = tid; i < Fdim; i += NTHREADS)         fcb[i] = fc_b[i];
    __syncthreads();

    const unsigned int wst_s = (unsigned int)__cvta_generic_to_shared(wst);

    // Phase-1 mapping: 2 m-groups (8 rows each) x 128 n-groups (2 packed cols)
    const int mg  = tid >> 7;      // 0..1
    const int ng2 = (tid & 127) * 2;
    // Phase-2 mapping: 8 m-groups x 32 f-groups (2m x 4f)
    const int mh = tid >> 5;
    const int fg = tid & 31;

    float* hc = hbufA;
    float* hn = hbufB;

    for (int s = 0; s < Tlen; ++s) {
        // ===== Phase 1: gates + h update, 2 chunks of 256 n-cols =====
        #pragma unroll 1
        for (int nc = 0; nc < 2; ++nc) {
            ull aR[8], aZ[8], aN[8], aI[8];
            #pragma unroll
            for (int i = 0; i < 8; ++i) { aR[i] = 0; aZ[i] = 0; aN[i] = 0; aI[i] = 0; }

            stage_gate(wst_s, 0, 0, nc, tid);
            cp_commit();

            #pragma unroll 1
            for (int b = 0; b < 40; ++b) {
                if (b + 1 < 40) stage_gate(wst_s, (b + 1) & 1, b + 1, nc, tid);
                cp_commit();
                cp_wait1();
                __syncthreads();
                const float* wb = wst + (b & 1) * (KB * 768);
                if (b < 8) gate_block(wb, xbuf, Fdim, b * KB, mg, ng2, aR, aZ, aI);
                else       gate_block(wb, hc,   Hdim, (b - 8) * KB, mg, ng2, aR, aZ, aN);
                __syncthreads();
            }

            // epilogue: gate nonlinearity + h update (this thread's 8m x 2n patch)
            const int col = nc * 256 + ng2;
            #pragma unroll
            for (int i = 0; i < 8; ++i) {
                const int m = mg * 8 + i;
                float2 R = unpack2(aR[i]), Z = unpack2(aZ[i]);
                float2 N = unpack2(aN[i]), I = unpack2(aI[i]);
                #pragma unroll
                for (int q = 0; q < 2; ++q) {
                    const int c = col + q;
                    const float rp = (q ? R.y : R.x) + brz[c];
                    const float zp = (q ? Z.y : Z.x) + brz[Hdim + c];
                    const float r = 1.f / (1.f + __expf(-rp));
                    const float z = 1.f / (1.f + __expf(-zp));
                    const float nv = tanhf((q ? I.y : I.x) + bin[c] +
                                           r * ((q ? N.y : N.x) + bhn[c]));
                    const float hp = hc[m * Hdim + c];
                    hn[m * Hdim + c] = (1.f - z) * nv + z * hp;
                }
            }
        }

        // ===== Phase 2: x_new = h_new @ fc_w^T + fc_b; emit output =====
        {
            ull acc[2][2] = {{0ull, 0ull}, {0ull, 0ull}};
            stage_fc(wst_s, 0, 0, tid);
            cp_commit();
            #pragma unroll 1
            for (int b = 0; b < 32; ++b) {
                if (b + 1 < 32) stage_fc(wst_s, (b + 1) & 1, b + 1, tid);
                cp_commit();
                cp_wait1();
                __syncthreads();
                const float* wb = wst + (b & 1) * (KB * 768);
                fc_block(wb, hn, b * KB, mh, fg * 4, acc);
                __syncthreads();
            }

            const int trow = Tlen - 1 - s;   // reference reverses time at the end
            const int f0 = fg * 4;
            #pragma unroll
            for (int i = 0; i < 2; ++i) {
                const int m = mh * 2 + i;
                #pragma unroll
                for (int p = 0; p < 2; ++p) {
                    float2 v = unpack2(acc[i][p]);
                    const float v0 = v.x + fcb[f0 + p * 2];
                    const float v1 = v.y + fcb[f0 + p * 2 + 1];
                    xbuf[m * Fdim + f0 + p * 2]     = v0;
                    xbuf[m * Fdim + f0 + p * 2 + 1] = v1;
                    *reinterpret_cast<float2*>(
                        &out[((size_t)(m0 + m) * Tlen + trow) * Fdim + f0 + p * 2]) =
                        make_float2(v0, v1);
                }
            }
        }
        // xbuf/hn writes are ordered before next step's reads by the first
        // __syncthreads inside the next pipeline loop.

        float* tmp = hc; hc = hn; hn = tmp;
    }
}

extern "C" void kernel_launch(void* const* d_in, const int* in_sizes, int n_in,
                              void* d_out, int out_size) {
    const float* hidden = (const float*)d_in[0];
    const float* w_ih   = (const float*)d_in[1];
    const float* w_hh   = (const float*)d_in[2];
    const float* b_ih   = (const float*)d_in[3];
    const float* b_hh   = (const float*)d_in[4];
    const float* fc_w   = (const float*)d_in[5];
    const float* fc_b   = (const float*)d_in[6];
    float* out = (float*)d_out;

    const int total = Hdim * G3H + Fdim * G3H + Hdim * Fdim;
    gru_setup_kernel<<<(total + 255) / 256, 256>>>(w_ih, w_hh, fc_w);

    const int smem_bytes =
        (2 * Mtile * Hdim + Mtile * Fdim + 2 * Hdim + Hdim + Hdim + Fdim +
         2 * KB * 768) * (int)sizeof(float);
    cudaFuncSetAttribute(gru_kernel, cudaFuncAttributeMaxDynamicSharedMemorySize, smem_bytes);
    gru_kernel<<<Bsz / Mtile, NTHREADS, smem_bytes>>>(hidden, b_ih, b_hh, fc_b, out);
}

// round 7
// speedup vs baseline: 1.1480x; 1.1480x over previous
#include <cuda_runtime.h>
#include <math.h>

#define Bsz   2048
#define Fdim  128
#define Hdim  512
#define Tlen  96
#define G3H   1536
#define Mtile 16
#define NTHREADS 256

typedef unsigned long long ull;

// Transposed weights (k-major) in device scratch, ~4MB, L2-resident.
__device__ __align__(16) float d_WhhT[Hdim * G3H];  // [k][n] k<512, n<1536
__device__ __align__(16) float d_WihT[Fdim * G3H];  // [k][n] k<128, n<1536
__device__ __align__(16) float d_FcwT[Hdim * Fdim]; // [k][f] k<512, f<128

// ---- packed f32x2 helpers ----
__device__ __forceinline__ ull bcast2(float a) {
    ull r; unsigned int u = __float_as_uint(a);
    asm("mov.b64 %0, {%1, %1};" : "=l"(r) : "r"(u));
    return r;
}
__device__ __forceinline__ void fma2(ull& d, ull a, ull b) {
    asm("fma.rn.f32x2 %0, %1, %2, %0;" : "+l"(d) : "l"(a), "l"(b));
}
__device__ __forceinline__ float2 unpack2(ull v) {
    unsigned int lo, hi;
    asm("mov.b64 {%0, %1}, %2;" : "=r"(lo), "=r"(hi) : "l"(v));
    return make_float2(__uint_as_float(lo), __uint_as_float(hi));
}

// One-time weight transpose
__global__ void gru_setup_kernel(const float* __restrict__ w_ih,
                                 const float* __restrict__ w_hh,
                                 const float* __restrict__ fc_w) {
    int idx = blockIdx.x * blockDim.x + threadIdx.x;
    if (idx < Hdim * G3H) {
        int k = idx / G3H, n = idx - k * G3H;
        d_WhhT[idx] = w_hh[n * Hdim + k];
    }
    int i2 = idx - Hdim * G3H;
    if (i2 >= 0 && i2 < Fdim * G3H) {
        int k = i2 / G3H, n = i2 - k * G3H;
        d_WihT[i2] = w_ih[n * Fdim + k];
    }
    int i3 = idx - Hdim * G3H - Fdim * G3H;
    if (i3 >= 0 && i3 < Hdim * Fdim) {
        int k = i3 / Fdim, f = i3 - k * Fdim;
        d_FcwT[i3] = fc_w[f * Hdim + k];
    }
}

// ---- register double-buffered 3-gate GEMM slab ----
// Per-thread tile: 4 m-rows x 2 n-cols (1 packed ull) x 3 gates.
// Weight buffers: 8 k-steps x 3 gates, A/B ping-pong (96 regs).
template<int LD, int NIT>
__device__ __forceinline__ void gemm3(
    const float* __restrict__ wbase,   // Wt + col (row k at wbase + k*G3H)
    const float* __restrict__ in,      // activations [m][LD] in smem
    int mrow0,
    ull (&aR)[4], ull (&aZ)[4], ull (&aX)[4])
{
    ull wA[8][3], wB[8][3];

    #pragma unroll
    for (int kk = 0; kk < 8; ++kk) {
        const float* w = wbase + (size_t)kk * G3H;
        wA[kk][0] = *reinterpret_cast<const ull*>(w);
        wA[kk][1] = *reinterpret_cast<const ull*>(w + 512);
        wA[kk][2] = *reinterpret_cast<const ull*>(w + 1024);
    }

    #pragma unroll 1
    for (int it = 0; it < NIT; it += 2) {
        // prefetch B <- iter it+1 (always valid: NIT even, it <= NIT-2)
        {
            const float* wr0 = wbase + (size_t)(it + 1) * 8 * G3H;
            #pragma unroll
            for (int kk = 0; kk < 8; ++kk) {
                const float* w = wr0 + (size_t)kk * G3H;
                wB[kk][0] = *reinterpret_cast<const ull*>(w);
                wB[kk][1] = *reinterpret_cast<const ull*>(w + 512);
                wB[kk][2] = *reinterpret_cast<const ull*>(w + 1024);
            }
        }
        // compute A @ iter it
        {
            const int k0 = it * 8;
            float4 av[4][2];
            #pragma unroll
            for (int i = 0; i < 4; ++i) {
                const float* row = in + (size_t)(mrow0 + i) * LD + k0;
                av[i][0] = *reinterpret_cast<const float4*>(row);
                av[i][1] = *reinterpret_cast<const float4*>(row + 4);
            }
            #pragma unroll
            for (int kk = 0; kk < 8; ++kk) {
                ull wr = wA[kk][0], wz = wA[kk][1], wn = wA[kk][2];
                #pragma unroll
                for (int i = 0; i < 4; ++i) {
                    float a = reinterpret_cast<const float*>(&av[i][kk >> 2])[kk & 3];
                    ull a2 = bcast2(a);
                    fma2(aR[i], a2, wr);
                    fma2(aZ[i], a2, wz);
                    fma2(aX[i], a2, wn);
                }
            }
        }
        // prefetch A <- iter it+2 (clamped; clamp loads are discarded)
        {
            const int nx = (it + 2 < NIT) ? (it + 2) : it;
            const float* wr0 = wbase + (size_t)nx * 8 * G3H;
            #pragma unroll
            for (int kk = 0; kk < 8; ++kk) {
                const float* w = wr0 + (size_t)kk * G3H;
                wA[kk][0] = *reinterpret_cast<const ull*>(w);
                wA[kk][1] = *reinterpret_cast<const ull*>(w + 512);
                wA[kk][2] = *reinterpret_cast<const ull*>(w + 1024);
            }
        }
        // compute B @ iter it+1
        {
            const int k0 = (it + 1) * 8;
            float4 av[4][2];
            #pragma unroll
            for (int i = 0; i < 4; ++i) {
                const float* row = in + (size_t)(mrow0 + i) * LD + k0;
                av[i][0] = *reinterpret_cast<const float4*>(row);
                av[i][1] = *reinterpret_cast<const float4*>(row + 4);
            }
            #pragma unroll
            for (int kk = 0; kk < 8; ++kk) {
                ull wr = wB[kk][0], wz = wB[kk][1], wn = wB[kk][2];
                #pragma unroll
                for (int i = 0; i < 4; ++i) {
                    float a = reinterpret_cast<const float*>(&av[i][kk >> 2])[kk & 3];
                    ull a2 = bcast2(a);
                    fma2(aR[i], a2, wr);
                    fma2(aZ[i], a2, wz);
                    fma2(aX[i], a2, wn);
                }
            }
        }
    }
}

__global__ __launch_bounds__(NTHREADS, 1)
void gru_kernel(const float* __restrict__ hidden,
                const float* __restrict__ b_ih,
                const float* __restrict__ b_hh,
                const float* __restrict__ fc_b,
                float* __restrict__ out) {
    extern __shared__ float smem[];
    float* hbufA = smem;                          // Mtile*Hdim
    float* hbufB = hbufA + Mtile * Hdim;          // Mtile*Hdim
    float* xbuf  = hbufB + Mtile * Hdim;          // Mtile*Fdim
    float* brz   = xbuf + Mtile * Fdim;           // 2*Hdim
    float* bin   = brz + 2 * Hdim;                // Hdim
    float* bhn   = bin + Hdim;                    // Hdim
    float* fcb   = bhn + Hdim;                    // Fdim

    const int tid = threadIdx.x;
    const int m0  = blockIdx.x * Mtile;

    for (int i = tid; i < Mtile * Hdim; i += NTHREADS) hbufA[i] = hidden[m0 * Hdim + i];
    for (int i = tid; i < Mtile * Fdim; i += NTHREADS) xbuf[i] = 0.f;
    for (int i = tid; i < 2 * Hdim; i += NTHREADS)     brz[i] = b_ih[i] + b_hh[i];
    for (int i = tid; i < Hdim; i += NTHREADS) {
        bin[i] = b_ih[2 * Hdim + i];
        bhn[i] = b_hh[2 * Hdim + i];
    }
    for (int i = tid; i < Fdim; i += NTHREADS)         fcb[i] = fc_b[i];
    __syncthreads();

    // Phase-1 mapping: 4 m-groups (4 rows) x 64 n-groups (2 cols); 4 chunks of 128 cols/gate
    const int mg    = tid >> 6;            // 0..3
    const int ng2   = (tid & 63) * 2;      // col within 128-chunk
    const int mrow0 = mg * 4;
    // Phase-2 mapping: 8 m-groups x 32 f-groups (2m x 4f)
    const int mh = tid >> 5;
    const int fg = tid & 31;
    const int f0 = fg * 4;

    float* hc = hbufA;
    float* hn = hbufB;

    for (int s = 0; s < Tlen; ++s) {
        // ===== Phase 1: gates + h update, 4 chunks of 128 n-cols per gate =====
        #pragma unroll 1
        for (int nc = 0; nc < 4; ++nc) {
            const int col = nc * 128 + ng2;

            ull aR[4], aZ[4], aN[4], aI[4];
            #pragma unroll
            for (int i = 0; i < 4; ++i) { aR[i] = 0; aZ[i] = 0; aN[i] = 0; aI[i] = 0; }

            // x contribution (K=128) -> aR, aZ, aI
            gemm3<Fdim, 16>(d_WihT + col, xbuf, mrow0, aR, aZ, aI);
            // h contribution (K=512) -> aR, aZ, aN
            gemm3<Hdim, 64>(d_WhhT + col, hc, mrow0, aR, aZ, aN);

            // epilogue: nonlinearity + h update on this thread's 4m x 2n patch
            const float2 br = *reinterpret_cast<const float2*>(&brz[col]);
            const float2 bz = *reinterpret_cast<const float2*>(&brz[Hdim + col]);
            const float2 bi = *reinterpret_cast<const float2*>(&bin[col]);
            const float2 bh = *reinterpret_cast<const float2*>(&bhn[col]);
            #pragma unroll
            for (int i = 0; i < 4; ++i) {
                const int m = mrow0 + i;
                float2 R = unpack2(aR[i]), Z = unpack2(aZ[i]);
                float2 N = unpack2(aN[i]), I = unpack2(aI[i]);
                float2 hp = *reinterpret_cast<const float2*>(&hc[m * Hdim + col]);

                float r0 = 1.f / (1.f + __expf(-(R.x + br.x)));
                float r1 = 1.f / (1.f + __expf(-(R.y + br.y)));
                float z0 = 1.f / (1.f + __expf(-(Z.x + bz.x)));
                float z1 = 1.f / (1.f + __expf(-(Z.y + bz.y)));
                float n0 = tanhf(I.x + bi.x + r0 * (N.x + bh.x));
                float n1 = tanhf(I.y + bi.y + r1 * (N.y + bh.y));
                float2 hv = make_float2((1.f - z0) * n0 + z0 * hp.x,
                                        (1.f - z1) * n1 + z1 * hp.y);
                *reinterpret_cast<float2*>(&hn[m * Hdim + col]) = hv;
            }
        }
        __syncthreads();   // hn complete

        // ===== Phase 2: x_new = h_new @ fc_w^T + fc_b (A/B pipelined) =====
        {
            ull acc[2][2] = {{0ull, 0ull}, {0ull, 0ull}};
            ulonglong2 fA[8], fB[8];
            const float* fw = d_FcwT + f0;

            #pragma unroll
            for (int kk = 0; kk < 8; ++kk)
                fA[kk] = *reinterpret_cast<const ulonglong2*>(fw + (size_t)kk * Fdim);

            #pragma unroll 1
            for (int it = 0; it < 64; it += 2) {
                #pragma unroll
                for (int kk = 0; kk < 8; ++kk)
                    fB[kk] = *reinterpret_cast<const ulonglong2*>(
                        fw + (size_t)((it + 1) * 8 + kk) * Fdim);
                {
                    const int k0 = it * 8;
                    float4 av[2][2];
                    #pragma unroll
                    for (int i = 0; i < 2; ++i) {
                        const float* row = hn + (size_t)(mh * 2 + i) * Hdim + k0;
                        av[i][0] = *reinterpret_cast<const float4*>(row);
                        av[i][1] = *reinterpret_cast<const float4*>(row + 4);
                    }
                    #pragma unroll
                    for (int kk = 0; kk < 8; ++kk) {
                        #pragma unroll
                        for (int i = 0; i < 2; ++i) {
                            float a = reinterpret_cast<const float*>(&av[i][kk >> 2])[kk & 3];
                            ull a2 = bcast2(a);
                            fma2(acc[i][0], a2, fA[kk].x);
                            fma2(acc[i][1], a2, fA[kk].y);
                        }
                    }
                }
                {
                    const int nx = (it + 2 < 64) ? (it + 2) : it;
                    #pragma unroll
                    for (int kk = 0; kk < 8; ++kk)
                        fA[kk] = *reinterpret_cast<const ulonglong2*>(
                            fw + (size_t)(nx * 8 + kk) * Fdim);
                }
                {
                    const int k0 = (it + 1) * 8;
                    float4 av[2][2];
                    #pragma unroll
                    for (int i = 0; i < 2; ++i) {
                        const float* row = hn + (size_t)(mh * 2 + i) * Hdim + k0;
                        av[i][0] = *reinterpret_cast<const float4*>(row);
                        av[i][1] = *reinterpret_cast<const float4*>(row + 4);
                    }
                    #pragma unroll
                    for (int kk = 0; kk < 8; ++kk) {
                        #pragma unroll
                        for (int i = 0; i < 2; ++i) {
                            float a = reinterpret_cast<const float*>(&av[i][kk >> 2])[kk & 3];
                            ull a2 = bcast2(a);
                            fma2(acc[i][0], a2, fB[kk].x);
                            fma2(acc[i][1], a2, fB[kk].y);
                        }
                    }
                }
            }

            const int trow = Tlen - 1 - s;   // reference reverses time at the end
            #pragma unroll
            for (int i = 0; i < 2; ++i) {
                const int m = mh * 2 + i;
                #pragma unroll
                for (int p = 0; p < 2; ++p) {
                    float2 v = unpack2(acc[i][p]);
                    const float v0 = v.x + fcb[f0 + p * 2];
                    const float v1 = v.y + fcb[f0 + p * 2 + 1];
                    xbuf[m * Fdim + f0 + p * 2]     = v0;
                    xbuf[m * Fdim + f0 + p * 2 + 1] = v1;
                    *reinterpret_cast<float2*>(
                        &out[((size_t)(m0 + m) * Tlen + trow) * Fdim + f0 + p * 2]) =
                        make_float2(v0, v1);
                }
            }
        }
        __syncthreads();   // xbuf complete before next step's phase 1

        float* tmp = hc; hc = hn; hn = tmp;
    }
}

extern "C" void kernel_launch(void* const* d_in, const int* in_sizes, int n_in,
                              void* d_out, int out_size) {
    const float* hidden = (const float*)d_in[0];
    const float* w_ih   = (const float*)d_in[1];
    const float* w_hh   = (const float*)d_in[2];
    const float* b_ih   = (const float*)d_in[3];
    const float* b_hh   = (const float*)d_in[4];
    const float* fc_w   = (const float*)d_in[5];
    const float* fc_b   = (const float*)d_in[6];
    float* out = (float*)d_out;

    const int total = Hdim * G3H + Fdim * G3H + Hdim * Fdim;
    gru_setup_kernel<<<(total + 255) / 256, 256>>>(w_ih, w_hh, fc_w);

    const int smem_bytes =
        (2 * Mtile * Hdim + Mtile * Fdim + 2 * Hdim + Hdim + Hdim + Fdim) * (int)sizeof(float);
    cudaFuncSetAttribute(gru_kernel, cudaFuncAttributeMaxDynamicSharedMemorySize, smem_bytes);
    gru_kernel<<<Bsz / Mtile, NTHREADS, smem_bytes>>>(hidden, b_ih, b_hh, fc_b, out);
}